// round 5
// baseline (speedup 1.0000x reference)
#include <cuda_runtime.h>

#define NS 512       // sequence length N
#define DD 64        // feature dim d
#define NB 64        // batch B
#define GTJ 64       // column tiles (8 wide each)
#define NDIAG 192    // 128 + 64 - 1 = 191, padded even
#define DEADC (-20000)
#define SENT 0xFFFFFFFFu

// 64 MB scratch: E[b,i,j] = exp(-||x_i - y_j||)
__device__ float g_E[(size_t)NB * NS * NS];

// ---------------------------------------------------------------------------
// Packed f32x2 FMA (Blackwell)
// ---------------------------------------------------------------------------
__device__ __forceinline__ void fma2(unsigned long long& d,
                                     unsigned long long a,
                                     unsigned long long b) {
    asm("fma.rn.f32x2 %0, %1, %2, %0;" : "+l"(d) : "l"(a), "l"(b));
}

// ---------------------------------------------------------------------------
// Stage 1: E[b,i,j] = exp(-sqrt(max(0, |x_i|^2 + |y_j|^2 - 2 x_i.y_j)))
// ---------------------------------------------------------------------------
__global__ void __launch_bounds__(256, 2)
cdist_kernel(const float* __restrict__ X, const float* __restrict__ Y) {
    __shared__ float Xs[64 * 64];
    __shared__ float Ys[64 * 64];
    __shared__ float xn[64], yn[64];

    const int b  = blockIdx.z;
    const int i0 = blockIdx.y * 64;
    const int j0 = blockIdx.x * 64;
    const int tid = threadIdx.y * 16 + threadIdx.x;

    const float* Xg = X + ((size_t)b * NS + i0) * DD;
    const float* Yg = Y + ((size_t)b * NS + j0) * DD;

    float4* Xs4 = reinterpret_cast<float4*>(Xs);
    float4* Ys4 = reinterpret_cast<float4*>(Ys);

#pragma unroll
    for (int t = 0; t < 4; ++t) {
        int lin = t * 256 + tid;
        int row = lin >> 4;
        int k4  = lin & 15;
        int sw  = k4 ^ (row & 15);
        Xs4[row * 16 + sw] = *reinterpret_cast<const float4*>(Xg + row * DD + k4 * 4);
        Ys4[row * 16 + sw] = *reinterpret_cast<const float4*>(Yg + row * DD + k4 * 4);
    }
    __syncthreads();

    if (tid < 128) {
        int r = tid & 63;
        const float4* P = (tid < 64) ? reinterpret_cast<const float4*>(Xs)
                                     : reinterpret_cast<const float4*>(Ys);
        float s = 0.0f;
#pragma unroll
        for (int k4 = 0; k4 < 16; ++k4) {
            float4 v = P[r * 16 + (k4 ^ (r & 15))];
            s += v.x * v.x + v.y * v.y + v.z * v.z + v.w * v.w;
        }
        if (tid < 64) xn[r] = s; else yn[r] = s;
    }
    __syncthreads();

    const int tx = threadIdx.x, ty = threadIdx.y;

    unsigned long long acc[4][4];
#pragma unroll
    for (int r = 0; r < 4; ++r)
#pragma unroll
        for (int c = 0; c < 4; ++c) acc[r][c] = 0ull;

    const ulonglong2* Xs2 = reinterpret_cast<const ulonglong2*>(Xs);
    const ulonglong2* Ys2 = reinterpret_cast<const ulonglong2*>(Ys);

#pragma unroll
    for (int k4 = 0; k4 < 16; ++k4) {
        ulonglong2 av[4], bv[4];
#pragma unroll
        for (int r = 0; r < 4; ++r) {
            int i = ty + 16 * r;
            av[r] = Xs2[i * 16 + (k4 ^ (i & 15))];
        }
#pragma unroll
        for (int c = 0; c < 4; ++c) {
            int j = tx + 16 * c;
            bv[c] = Ys2[j * 16 + (k4 ^ (j & 15))];
        }
#pragma unroll
        for (int r = 0; r < 4; ++r)
#pragma unroll
            for (int c = 0; c < 4; ++c) {
                fma2(acc[r][c], av[r].x, bv[c].x);
                fma2(acc[r][c], av[r].y, bv[c].y);
            }
    }

    float* Eout = g_E + (size_t)b * NS * NS;
#pragma unroll
    for (int r = 0; r < 4; ++r) {
        int i = ty + 16 * r;
#pragma unroll
        for (int c = 0; c < 4; ++c) {
            int j = tx + 16 * c;
            float lo = __uint_as_float((unsigned)(acc[r][c] & 0xffffffffull));
            float hi = __uint_as_float((unsigned)(acc[r][c] >> 32));
            float d2 = xn[i] + yn[j] - 2.0f * (lo + hi);
            float dist = sqrtf(fmaxf(d2, 0.0f));
            Eout[(size_t)(i0 + i) * NS + (j0 + j)] =
                exp2f(-1.4426950408889634f * dist);
        }
    }
}

// ---------------------------------------------------------------------------
// Stage 2: weight-domain soft-DTW, barrier-free wavefront.
// Frontier handoff ti-1 -> ti via __shfl_up_sync within warps; 3 warp
// boundaries via one-shot SMEM mailboxes (st.release / ld.acquire spin).
// ---------------------------------------------------------------------------
__device__ __forceinline__ float exp2i_neg(int e) {
    return (e >= -126) ? __int_as_float((e + 127) << 23) : 0.0f;
}
__device__ __forceinline__ int fexp(float m) {
    return ((__float_as_int(m) >> 23) & 0xff) - 127;
}
__device__ __forceinline__ unsigned packc(int c0, int c1) {
    return ((unsigned)(c0 + 0x8000) << 16) | (unsigned)(c1 + 0x8000);
}

__device__ __forceinline__ void subtile4(
    float4 top, int sTop,
    float& cornE, int& cornC2,
    float (&left)[4], int& leftC2,
    float4 e0, float4 e1, float4 e2, float4 e3,
    float4& outB, int& outC2)
{
    int c2 = max(max(sTop, cornC2), leftC2);
    const float ft = exp2i_neg(sTop   - c2);
    const float fc = exp2i_neg(cornC2 - c2);
    const float fl = exp2i_neg(leftC2 - c2);

    float prev[5];
    prev[0] = cornE * fc;
    prev[1] = top.x * ft; prev[2] = top.y * ft;
    prev[3] = top.z * ft; prev[4] = top.w * ft;
    float lE[4] = {left[0] * fl, left[1] * fl, left[2] * fl, left[3] * fl};
    const float newCorn = prev[4];

    float4 dt[4] = {e0, e1, e2, e3};
    float right[4];
#pragma unroll
    for (int a = 0; a < 4; ++a) {
        const float dd0 = dt[a].x, dd1 = dt[a].y, dd2 = dt[a].z, dd3 = dt[a].w;
        float carry = prev[0];
        prev[0] = lE[a];
        float s;
        s = (carry + prev[1]) + prev[0]; carry = prev[1]; prev[1] = dd0 * s;
        s = (carry + prev[2]) + prev[1]; carry = prev[2]; prev[2] = dd1 * s;
        s = (carry + prev[3]) + prev[2]; carry = prev[3]; prev[3] = dd2 * s;
        s = (carry + prev[4]) + prev[3];                  prev[4] = dd3 * s;
        right[a] = prev[4];
    }

    float mr = fmaxf(fmaxf(prev[1], prev[2]), fmaxf(prev[3], prev[4]));
    int emr = fexp(mr);
    float rsr = __int_as_float((127 - emr) << 23);
    outB = make_float4(prev[1] * rsr, prev[2] * rsr, prev[3] * rsr, prev[4] * rsr);
    outC2 = (mr > 0.0f) ? (c2 + emr) : DEADC;

    float mc = fmaxf(fmaxf(right[0], right[1]), fmaxf(right[2], right[3]));
    int emc = fexp(mc);
    float rsc = __int_as_float((127 - emc) << 23);
    left[0] = right[0] * rsc; left[1] = right[1] * rsc;
    left[2] = right[2] * rsc; left[3] = right[3] * rsc;
    leftC2 = (mc > 0.0f) ? (c2 + emc) : DEADC;

    int ec = fexp(newCorn);
    cornE  = newCorn * __int_as_float((127 - ec) << 23);
    cornC2 = (newCorn > 0.0f) ? (c2 + ec) : DEADC;
}

struct DPState {
    float left[4];
    int leftC2;
    float cornE;
    int cornC2;
    float4 pB0, pB1;      // previous-iteration bottom-row outputs
    unsigned pPack;       // packed (c0, c1)
};

__device__ __forceinline__ void dp_step(
    int kd, int ti, int wid, int lane, int b,
    const float* __restrict__ Erow0,
    float4 (&cb)[8], float4 (&nb)[8],
    float4 (*bndA)[GTJ], float4 (*bndB)[GTJ], unsigned (*bndM)[GTJ],
    DPState& st, float* __restrict__ out)
{
    const int tj  = kd - ti;
    const int tjr = (tj < 0) ? 0 : (tj > GTJ - 1 ? GTJ - 1 : tj);

    // --- Top frontier: shfl from lane-1 (its previous-iteration outputs). ---
    float4 t0, t1; unsigned mk;
    t0.x = __shfl_up_sync(0xffffffffu, st.pB0.x, 1);
    t0.y = __shfl_up_sync(0xffffffffu, st.pB0.y, 1);
    t0.z = __shfl_up_sync(0xffffffffu, st.pB0.z, 1);
    t0.w = __shfl_up_sync(0xffffffffu, st.pB0.w, 1);
    t1.x = __shfl_up_sync(0xffffffffu, st.pB1.x, 1);
    t1.y = __shfl_up_sync(0xffffffffu, st.pB1.y, 1);
    t1.z = __shfl_up_sync(0xffffffffu, st.pB1.z, 1);
    t1.w = __shfl_up_sync(0xffffffffu, st.pB1.w, 1);
    mk   = __shfl_up_sync(0xffffffffu, st.pPack, 1);

    if (lane == 0) {
        if (wid == 0) {
            t0 = make_float4(0.f, 0.f, 0.f, 0.f);
            t1 = t0;
            mk = packc(DEADC, DEADC);
        } else {
            unsigned addr = (unsigned)__cvta_generic_to_shared(&bndM[wid - 1][tjr]);
            unsigned m;
            do {
                asm volatile("ld.acquire.cta.shared.u32 %0, [%1];"
                             : "=r"(m) : "r"(addr) : "memory");
            } while (m == SENT);
            mk = m;
            t0 = bndA[wid - 1][tjr];
            t1 = bndB[wid - 1][tjr];
        }
    }
    int s0 = (int)(mk >> 16) - 0x8000;
    int s1 = (int)(mk & 0xffffu) - 0x8000;

    if (tj == 0) {   // activation reset (predicated)
        st.left[0] = st.left[1] = st.left[2] = st.left[3] = 0.0f;
        st.leftC2 = DEADC;
        st.cornE  = (ti == 0) ? 1.0f : 0.0f;
        st.cornC2 = (ti == 0) ? 0 : DEADC;
    }

    // Prefetch next tile (clamped, always issued) into the other buffer.
    {
        int tn = tj + 1;
        int cb8 = ((tn < 0) ? 0 : (tn > GTJ - 1 ? GTJ - 1 : tn)) * 8;
#pragma unroll
        for (int a = 0; a < 4; ++a) {
            nb[2 * a]     = *reinterpret_cast<const float4*>(Erow0 + a * NS + cb8);
            nb[2 * a + 1] = *reinterpret_cast<const float4*>(Erow0 + a * NS + cb8 + 4);
        }
    }

    float4 b0, b1; int c0, c1;
    subtile4(t0, s0, st.cornE, st.cornC2, st.left, st.leftC2,
             cb[0], cb[2], cb[4], cb[6], b0, c0);
    subtile4(t1, s1, st.cornE, st.cornC2, st.left, st.leftC2,
             cb[1], cb[3], cb[5], cb[7], b1, c1);

    unsigned np = packc(c0, c1);
    st.pB0 = b0; st.pB1 = b1; st.pPack = np;

    // Boundary producers: lanes 31 of warps 0..2, one-shot mailbox per tj.
    if (lane == 31 && wid < 3 && (unsigned)tj < (unsigned)GTJ) {
        bndA[wid][tj] = b0;
        bndB[wid][tj] = b1;
        unsigned addr = (unsigned)__cvta_generic_to_shared(&bndM[wid][tj]);
        asm volatile("st.release.cta.shared.u32 [%0], %1;"
                     :: "r"(addr), "r"(np) : "memory");
    }

    // Final cell: thread 127, tile (127,63) at kd = 190.
    if (kd == 2 * GTJ + 62 && ti == 127) {
        float e = fmaxf(b1.w, 1.17549435e-38f);
        out[b] = -(log2f(e) + (float)c1) * 0.69314718055994530942f;
    }
}

__global__ void __launch_bounds__(128, 1)
dp_kernel(float* __restrict__ out) {
    const int b = blockIdx.x;
    const float* Eb = g_E + (size_t)b * NS * NS;

    __shared__ __align__(16) float4 bndA[3][GTJ];
    __shared__ __align__(16) float4 bndB[3][GTJ];
    __shared__ unsigned bndM[3][GTJ];

    const int ti = threadIdx.x;
    const int wid = ti >> 5, lane = ti & 31;
    const float* Erow0 = Eb + (size_t)(ti * 4) * NS;

    // Init mailbox markers to sentinel.
    for (int s = ti; s < 3 * GTJ; s += 128) (&bndM[0][0])[s] = SENT;

    float4 bufA[8], bufB[8];
#pragma unroll
    for (int a = 0; a < 8; ++a) {
        bufA[a] = make_float4(0.f, 0.f, 0.f, 0.f);
        bufB[a] = bufA[a];
    }
#pragma unroll
    for (int a = 0; a < 4; ++a) {   // preload tile tj=0
        bufA[2 * a]     = *reinterpret_cast<const float4*>(Erow0 + a * NS);
        bufA[2 * a + 1] = *reinterpret_cast<const float4*>(Erow0 + a * NS + 4);
    }

    DPState st;
    st.left[0] = st.left[1] = st.left[2] = st.left[3] = 0.0f;
    st.leftC2 = DEADC;
    st.cornE = 0.0f; st.cornC2 = DEADC;
    st.pB0 = make_float4(0.f, 0.f, 0.f, 0.f);
    st.pB1 = st.pB0;
    st.pPack = packc(DEADC, DEADC);

    __syncthreads();   // sentinel init visible to all warps (the only barrier)

    for (int kd = 0; kd < NDIAG; kd += 2) {
        dp_step(kd,     ti, wid, lane, b, Erow0, bufA, bufB,
                bndA, bndB, bndM, st, out);
        dp_step(kd + 1, ti, wid, lane, b, Erow0, bufB, bufA,
                bndA, bndB, bndM, st, out);
    }
}

// ---------------------------------------------------------------------------
extern "C" void kernel_launch(void* const* d_in, const int* in_sizes, int n_in,
                              void* d_out, int out_size) {
    (void)in_sizes; (void)n_in; (void)out_size;
    const float* X = (const float*)d_in[0];
    const float* Y = (const float*)d_in[1];
    float* out = (float*)d_out;

    dim3 g1(NS / 64, NS / 64, NB);   // (8, 8, 64)
    dim3 b1(16, 16);
    cdist_kernel<<<g1, b1>>>(X, Y);

    dp_kernel<<<NB, 128>>>(out);
}

// round 6
// speedup vs baseline: 1.6367x; 1.6367x over previous
#include <cuda_runtime.h>

#define NS 512       // sequence length N
#define DD 64        // feature dim d
#define NB 64        // batch B
#define GTJ 64       // column tiles (8 wide each)
#define NDIAG 192    // 128 + 64 - 1 = 191, padded even
#define C2_NEG (-0x40000000)
#define NGRP 4       // independent batches per CTA (one warp per batch per SMSP)

// 64 MB scratch: E[b,i,j] = exp(-||x_i - y_j||)
__device__ float g_E[(size_t)NB * NS * NS];

// ---------------------------------------------------------------------------
// Packed f32x2 FMA (Blackwell)
// ---------------------------------------------------------------------------
__device__ __forceinline__ void fma2(unsigned long long& d,
                                     unsigned long long a,
                                     unsigned long long b) {
    asm("fma.rn.f32x2 %0, %1, %2, %0;" : "+l"(d) : "l"(a), "l"(b));
}

// ---------------------------------------------------------------------------
// Stage 1: E[b,i,j] = exp(-sqrt(max(0, |x_i|^2 + |y_j|^2 - 2 x_i.y_j)))
// ---------------------------------------------------------------------------
__global__ void __launch_bounds__(256, 2)
cdist_kernel(const float* __restrict__ X, const float* __restrict__ Y) {
    __shared__ float Xs[64 * 64];
    __shared__ float Ys[64 * 64];
    __shared__ float xn[64], yn[64];

    const int b  = blockIdx.z;
    const int i0 = blockIdx.y * 64;
    const int j0 = blockIdx.x * 64;
    const int tid = threadIdx.y * 16 + threadIdx.x;

    const float* Xg = X + ((size_t)b * NS + i0) * DD;
    const float* Yg = Y + ((size_t)b * NS + j0) * DD;

    float4* Xs4 = reinterpret_cast<float4*>(Xs);
    float4* Ys4 = reinterpret_cast<float4*>(Ys);

#pragma unroll
    for (int t = 0; t < 4; ++t) {
        int lin = t * 256 + tid;
        int row = lin >> 4;
        int k4  = lin & 15;
        int sw  = k4 ^ (row & 15);
        Xs4[row * 16 + sw] = *reinterpret_cast<const float4*>(Xg + row * DD + k4 * 4);
        Ys4[row * 16 + sw] = *reinterpret_cast<const float4*>(Yg + row * DD + k4 * 4);
    }
    __syncthreads();

    if (tid < 128) {
        int r = tid & 63;
        const float4* P = (tid < 64) ? reinterpret_cast<const float4*>(Xs)
                                     : reinterpret_cast<const float4*>(Ys);
        float s = 0.0f;
#pragma unroll
        for (int k4 = 0; k4 < 16; ++k4) {
            float4 v = P[r * 16 + (k4 ^ (r & 15))];
            s += v.x * v.x + v.y * v.y + v.z * v.z + v.w * v.w;
        }
        if (tid < 64) xn[r] = s; else yn[r] = s;
    }
    __syncthreads();

    const int tx = threadIdx.x, ty = threadIdx.y;

    unsigned long long acc[4][4];
#pragma unroll
    for (int r = 0; r < 4; ++r)
#pragma unroll
        for (int c = 0; c < 4; ++c) acc[r][c] = 0ull;

    const ulonglong2* Xs2 = reinterpret_cast<const ulonglong2*>(Xs);
    const ulonglong2* Ys2 = reinterpret_cast<const ulonglong2*>(Ys);

#pragma unroll
    for (int k4 = 0; k4 < 16; ++k4) {
        ulonglong2 av[4], bv[4];
#pragma unroll
        for (int r = 0; r < 4; ++r) {
            int i = ty + 16 * r;
            av[r] = Xs2[i * 16 + (k4 ^ (i & 15))];
        }
#pragma unroll
        for (int c = 0; c < 4; ++c) {
            int j = tx + 16 * c;
            bv[c] = Ys2[j * 16 + (k4 ^ (j & 15))];
        }
#pragma unroll
        for (int r = 0; r < 4; ++r)
#pragma unroll
            for (int c = 0; c < 4; ++c) {
                fma2(acc[r][c], av[r].x, bv[c].x);
                fma2(acc[r][c], av[r].y, bv[c].y);
            }
    }

    float* Eout = g_E + (size_t)b * NS * NS;
#pragma unroll
    for (int r = 0; r < 4; ++r) {
        int i = ty + 16 * r;
#pragma unroll
        for (int c = 0; c < 4; ++c) {
            int j = tx + 16 * c;
            float lo = __uint_as_float((unsigned)(acc[r][c] & 0xffffffffull));
            float hi = __uint_as_float((unsigned)(acc[r][c] >> 32));
            float d2 = xn[i] + yn[j] - 2.0f * (lo + hi);
            float dist = sqrtf(fmaxf(d2, 0.0f));
            Eout[(size_t)(i0 + i) * NS + (j0 + j)] =
                exp2f(-1.4426950408889634f * dist);
        }
    }
}

// ---------------------------------------------------------------------------
// Stage 2: weight-domain soft-DTW with binary scaling.
// 512 threads/CTA = 4 independent batches (one warp per batch per SMSP so
// the 4 DP wavefronts fill each other's RAW-latency gaps). Within a batch
// group: 128 threads, each owns 4 DP rows, 4x8 tile per diagonal as two 4x4
// sub-tiles, branchless wavefront, one __syncthreads per diagonal.
// ---------------------------------------------------------------------------
__device__ __forceinline__ float exp2i_neg(int e) {
    return (e >= -126) ? __int_as_float((e + 127) << 23) : 0.0f;
}
__device__ __forceinline__ int fexp(float m) {
    return ((__float_as_int(m) >> 23) & 0xff) - 127;
}

__device__ __forceinline__ void subtile4(
    float4 top, int sTop,
    float& cornE, int& cornC2,
    float (&left)[4], int& leftC2,
    float4 e0, float4 e1, float4 e2, float4 e3,
    float4& outB, int& outC2)
{
    int c2 = max(max(sTop, cornC2), leftC2);
    const float ft = exp2i_neg(sTop   - c2);
    const float fc = exp2i_neg(cornC2 - c2);
    const float fl = exp2i_neg(leftC2 - c2);

    float prev[5];
    prev[0] = cornE * fc;
    prev[1] = top.x * ft; prev[2] = top.y * ft;
    prev[3] = top.z * ft; prev[4] = top.w * ft;
    float lE[4] = {left[0] * fl, left[1] * fl, left[2] * fl, left[3] * fl};
    const float newCorn = prev[4];

    float4 dt[4] = {e0, e1, e2, e3};
    float right[4];
#pragma unroll
    for (int a = 0; a < 4; ++a) {
        const float dd0 = dt[a].x, dd1 = dt[a].y, dd2 = dt[a].z, dd3 = dt[a].w;
        float carry = prev[0];
        prev[0] = lE[a];
        float s;
        s = (carry + prev[1]) + prev[0]; carry = prev[1]; prev[1] = dd0 * s;
        s = (carry + prev[2]) + prev[1]; carry = prev[2]; prev[2] = dd1 * s;
        s = (carry + prev[3]) + prev[2]; carry = prev[3]; prev[3] = dd2 * s;
        s = (carry + prev[4]) + prev[3];                  prev[4] = dd3 * s;
        right[a] = prev[4];
    }

    // Renorm bottom row group.
    float mr = fmaxf(fmaxf(prev[1], prev[2]), fmaxf(prev[3], prev[4]));
    int emr = fexp(mr);
    float rsr = __int_as_float((127 - emr) << 23);
    outB = make_float4(prev[1] * rsr, prev[2] * rsr, prev[3] * rsr, prev[4] * rsr);
    outC2 = (mr > 0.0f) ? (c2 + emr) : C2_NEG;

    // Renorm right column group -> left frontier for the next sub-tile.
    float mc = fmaxf(fmaxf(right[0], right[1]), fmaxf(right[2], right[3]));
    int emc = fexp(mc);
    float rsc = __int_as_float((127 - emc) << 23);
    left[0] = right[0] * rsc; left[1] = right[1] * rsc;
    left[2] = right[2] * rsc; left[3] = right[3] * rsc;
    leftC2 = (mc > 0.0f) ? (c2 + emc) : C2_NEG;

    // Corner: own-exponent renorm (scale must track magnitude).
    int ec = fexp(newCorn);
    cornE  = newCorn * __int_as_float((127 - ec) << 23);
    cornC2 = (newCorn > 0.0f) ? (c2 + ec) : C2_NEG;
}

__device__ __forceinline__ void dp_step(
    int kd, int ti, const float* __restrict__ Erow0,
    float4 (&cb)[8], float4 (&nb)[8],
    float4 (*rowE4)[2 * GTJ + 2], int (*rowC2s)[2 * GTJ + 4],
    float (&left)[4], int& leftC2, float& cornE, int& cornC2)
{
    const int tj  = kd - ti;
    const int wb  = kd & 1, rb = wb ^ 1;
    const bool act = (unsigned)tj < (unsigned)GTJ;
    const int tjr = (tj < 0) ? 0 : (tj > GTJ - 1 ? GTJ - 1 : tj);

    // Top frontier (pre-zeroed parities provide the i = -1 boundary).
    float4 t0 = rowE4[rb][2 * tjr];
    float4 t1 = rowE4[rb][2 * tjr + 1];
    int    s0 = rowC2s[rb][2 * tjr];
    int    s1 = rowC2s[rb][2 * tjr + 1];

    // Activation reset (predicated selects, no divergence machinery).
    if (tj == 0) {
        left[0] = left[1] = left[2] = left[3] = 0.0f;
        leftC2 = C2_NEG;
        cornE  = (ti == 0) ? 1.0f : 0.0f;
        cornC2 = (ti == 0) ? 0 : C2_NEG;
    }

    // Prefetch next tile (tj+1) into the other buffer (clamped, always issued).
    {
        int tn = tj + 1;
        int cb8 = ((tn < 0) ? 0 : (tn > GTJ - 1 ? GTJ - 1 : tn)) * 8;
#pragma unroll
        for (int a = 0; a < 4; ++a) {
            nb[2 * a]     = *reinterpret_cast<const float4*>(Erow0 + a * NS + cb8);
            nb[2 * a + 1] = *reinterpret_cast<const float4*>(Erow0 + a * NS + cb8 + 4);
        }
    }

    float4 b0, b1; int c0, c1;
    subtile4(t0, s0, cornE, cornC2, left, leftC2, cb[0], cb[2], cb[4], cb[6], b0, c0);
    subtile4(t1, s1, cornE, cornC2, left, leftC2, cb[1], cb[3], cb[5], cb[7], b1, c1);

    const int ws = act ? 2 * tj : 2 * GTJ;   // dummy slot 128/129 when inactive
    rowE4[wb][ws]     = b0;
    rowE4[wb][ws + 1] = b1;
    rowC2s[wb][ws]     = c0;
    rowC2s[wb][ws + 1] = c1;
    __syncthreads();
}

__global__ void __launch_bounds__(128 * NGRP, 1)
dp_kernel(float* __restrict__ out) {
    const int tid = threadIdx.x;
    const int g   = tid >> 7;          // batch group 0..3 (warps 4g..4g+3)
    const int ti  = tid & 127;         // tile row within group
    const int b   = blockIdx.x * NGRP + g;
    const float* Eb = g_E + (size_t)b * NS * NS;

    __shared__ __align__(16) float4 rowE4s[NGRP][2][2 * GTJ + 2];
    __shared__ int rowC2ss[NGRP][2][2 * GTJ + 4];

    float4 (*rowE4)[2 * GTJ + 2] = rowE4s[g];
    int    (*rowC2s)[2 * GTJ + 4] = rowC2ss[g];

    const int i0 = ti * 4;
    const float* Erow0 = Eb + (size_t)i0 * NS;

    // Pre-zero both parities of all groups (i = -1 boundary: W=0, scale C2_NEG).
    {
        float4 z = make_float4(0.f, 0.f, 0.f, 0.f);
        float4* re = &rowE4s[0][0][0];
        for (int s = tid; s < NGRP * 2 * (2 * GTJ + 2); s += 128 * NGRP) re[s] = z;
        int* rc = &rowC2ss[0][0][0];
        for (int s = tid; s < NGRP * 2 * (2 * GTJ + 4); s += 128 * NGRP) rc[s] = C2_NEG;
    }

    float4 bufA[8], bufB[8];
#pragma unroll
    for (int a = 0; a < 8; ++a) {
        bufA[a] = make_float4(0.f, 0.f, 0.f, 0.f);
        bufB[a] = bufA[a];
    }
    // Preload tile tj=0 into bufA (only thread ti=0 consumes it un-refreshed).
#pragma unroll
    for (int a = 0; a < 4; ++a) {
        bufA[2 * a]     = *reinterpret_cast<const float4*>(Erow0 + a * NS);
        bufA[2 * a + 1] = *reinterpret_cast<const float4*>(Erow0 + a * NS + 4);
    }

    float left[4] = {0.f, 0.f, 0.f, 0.f};
    int leftC2 = C2_NEG;
    float cornE = 0.f;
    int cornC2 = C2_NEG;

    __syncthreads();

    for (int kd = 0; kd < NDIAG; kd += 2) {
        dp_step(kd,     ti, Erow0, bufA, bufB, rowE4, rowC2s,
                left, leftC2, cornE, cornC2);
        dp_step(kd + 1, ti, Erow0, bufB, bufA, rowE4, rowC2s,
                left, leftC2, cornE, cornC2);
    }

    // Thread ti=127 wrote its last tile (tj=63) at kd=190 (parity 0), slot 127.
    if (ti == 0) {
        float e  = fmaxf(rowE4[0][127].w, 1.17549435e-38f);
        float c2 = (float)rowC2s[0][127];
        out[b] = -(log2f(e) + c2) * 0.69314718055994530942f;
    }
}

// ---------------------------------------------------------------------------
extern "C" void kernel_launch(void* const* d_in, const int* in_sizes, int n_in,
                              void* d_out, int out_size) {
    (void)in_sizes; (void)n_in; (void)out_size;
    const float* X = (const float*)d_in[0];
    const float* Y = (const float*)d_in[1];
    float* out = (float*)d_out;

    dim3 g1(NS / 64, NS / 64, NB);   // (8, 8, 64)
    dim3 b1(16, 16);
    cdist_kernel<<<g1, b1>>>(X, Y);

    dp_kernel<<<NB / NGRP, 128 * NGRP>>>(out);
}

// round 7
// speedup vs baseline: 3.2571x; 1.9900x over previous
#include <cuda_runtime.h>

#define NS 512       // sequence length N
#define DD 64        // feature dim d
#define NB 64        // batch B
#define GTJ 64       // column tiles (8 wide each)
#define NDIAG 192    // 128 + 64 - 1 = 191, padded even
#define C2_NEG (-0x40000000)
#define SHIFT 90     // prescale: align tile inputs near 2^90 for headroom

// 64 MB scratch: E[b,i,j] = exp(-||x_i - y_j||)
__device__ float g_E[(size_t)NB * NS * NS];

// ---------------------------------------------------------------------------
// Packed f32x2 FMA (Blackwell)
// ---------------------------------------------------------------------------
__device__ __forceinline__ void fma2(unsigned long long& d,
                                     unsigned long long a,
                                     unsigned long long b) {
    asm("fma.rn.f32x2 %0, %1, %2, %0;" : "+l"(d) : "l"(a), "l"(b));
}

// ---------------------------------------------------------------------------
// Stage 1: E[b,i,j] = exp(-sqrt(max(0, |x_i|^2 + |y_j|^2 - 2 x_i.y_j)))
// (unchanged from R4 — proven at ~65us; stage-2 is the current bottleneck)
// ---------------------------------------------------------------------------
__global__ void __launch_bounds__(256, 2)
cdist_kernel(const float* __restrict__ X, const float* __restrict__ Y) {
    __shared__ float Xs[64 * 64];
    __shared__ float Ys[64 * 64];
    __shared__ float xn[64], yn[64];

    const int b  = blockIdx.z;
    const int i0 = blockIdx.y * 64;
    const int j0 = blockIdx.x * 64;
    const int tid = threadIdx.y * 16 + threadIdx.x;

    const float* Xg = X + ((size_t)b * NS + i0) * DD;
    const float* Yg = Y + ((size_t)b * NS + j0) * DD;

    float4* Xs4 = reinterpret_cast<float4*>(Xs);
    float4* Ys4 = reinterpret_cast<float4*>(Ys);

#pragma unroll
    for (int t = 0; t < 4; ++t) {
        int lin = t * 256 + tid;
        int row = lin >> 4;
        int k4  = lin & 15;
        int sw  = k4 ^ (row & 15);
        Xs4[row * 16 + sw] = *reinterpret_cast<const float4*>(Xg + row * DD + k4 * 4);
        Ys4[row * 16 + sw] = *reinterpret_cast<const float4*>(Yg + row * DD + k4 * 4);
    }
    __syncthreads();

    if (tid < 128) {
        int r = tid & 63;
        const float4* P = (tid < 64) ? reinterpret_cast<const float4*>(Xs)
                                     : reinterpret_cast<const float4*>(Ys);
        float s = 0.0f;
#pragma unroll
        for (int k4 = 0; k4 < 16; ++k4) {
            float4 v = P[r * 16 + (k4 ^ (r & 15))];
            s += v.x * v.x + v.y * v.y + v.z * v.z + v.w * v.w;
        }
        if (tid < 64) xn[r] = s; else yn[r] = s;
    }
    __syncthreads();

    const int tx = threadIdx.x, ty = threadIdx.y;

    unsigned long long acc[4][4];
#pragma unroll
    for (int r = 0; r < 4; ++r)
#pragma unroll
        for (int c = 0; c < 4; ++c) acc[r][c] = 0ull;

    const ulonglong2* Xs2 = reinterpret_cast<const ulonglong2*>(Xs);
    const ulonglong2* Ys2 = reinterpret_cast<const ulonglong2*>(Ys);

#pragma unroll
    for (int k4 = 0; k4 < 16; ++k4) {
        ulonglong2 av[4], bv[4];
#pragma unroll
        for (int r = 0; r < 4; ++r) {
            int i = ty + 16 * r;
            av[r] = Xs2[i * 16 + (k4 ^ (i & 15))];
        }
#pragma unroll
        for (int c = 0; c < 4; ++c) {
            int j = tx + 16 * c;
            bv[c] = Ys2[j * 16 + (k4 ^ (j & 15))];
        }
#pragma unroll
        for (int r = 0; r < 4; ++r)
#pragma unroll
            for (int c = 0; c < 4; ++c) {
                fma2(acc[r][c], av[r].x, bv[c].x);
                fma2(acc[r][c], av[r].y, bv[c].y);
            }
    }

    float* Eout = g_E + (size_t)b * NS * NS;
#pragma unroll
    for (int r = 0; r < 4; ++r) {
        int i = ty + 16 * r;
#pragma unroll
        for (int c = 0; c < 4; ++c) {
            int j = tx + 16 * c;
            float lo = __uint_as_float((unsigned)(acc[r][c] & 0xffffffffull));
            float hi = __uint_as_float((unsigned)(acc[r][c] >> 32));
            float d2 = xn[i] + yn[j] - 2.0f * (lo + hi);
            float dist = sqrtf(fmaxf(d2, 0.0f));
            Eout[(size_t)(i0 + i) * NS + (j0 + j)] =
                exp2f(-1.4426950408889634f * dist);
        }
    }
}

// ---------------------------------------------------------------------------
// Stage 2: weight-domain soft-DTW, binary scaling, 64 CTAs x 128 threads.
// Per diagonal: one un-split 4x8 tile per thread (short DAG), inputs aligned
// to 2^SHIFT, ONE merged renorm for row+col outputs, corner own-exponent.
// ---------------------------------------------------------------------------
__device__ __forceinline__ float exp2i_s(int e) {
    // 2^e for e <= ~104, flushing below 2^-126
    return (e >= -126) ? __int_as_float((e + 127) << 23) : 0.0f;
}
__device__ __forceinline__ int fexp(float m) {
    return ((__float_as_int(m) >> 23) & 0xff) - 127;
}

__device__ __forceinline__ void dp_step(
    int kd, int ti, const float* __restrict__ Erow0,
    float4 (&cb)[8], float4 (&nb)[8],
    float4 (*rowE4)[2 * GTJ + 2], int (*rowC2)[GTJ + 2],
    float (&left)[4], int& leftC2, float& cornE, int& cornC2,
    float* __restrict__ outp)
{
    const int tj  = kd - ti;
    const int wb  = kd & 1, rb = wb ^ 1;
    const bool act = (unsigned)tj < (unsigned)GTJ;
    const int tjr = (tj < 0) ? 0 : (tj > GTJ - 1 ? GTJ - 1 : tj);

    // Top frontier: 8 mantissas + one shared scale (pre-zeroed = boundary).
    float4 t0 = rowE4[rb][2 * tjr];
    float4 t1 = rowE4[rb][2 * tjr + 1];
    int  sTop = rowC2[rb][tjr];

    if (tj == 0) {   // activation reset (predicated)
        left[0] = left[1] = left[2] = left[3] = 0.0f;
        leftC2 = C2_NEG;
        cornE  = (ti == 0) ? 1.0f : 0.0f;
        cornC2 = (ti == 0) ? 0 : C2_NEG;
    }

    // Prefetch next tile (clamped, always issued) into the other buffer.
    {
        int tn = tj + 1;
        int c8 = ((tn < 0) ? 0 : (tn > GTJ - 1 ? GTJ - 1 : tn)) * 8;
#pragma unroll
        for (int a = 0; a < 4; ++a) {
            nb[2 * a]     = *reinterpret_cast<const float4*>(Erow0 + a * NS + c8);
            nb[2 * a + 1] = *reinterpret_cast<const float4*>(Erow0 + a * NS + c8 + 4);
        }
    }

    // Align the three scale groups near 2^SHIFT (headroom for 8 un-renormed cols).
    int c2 = max(max(sTop, cornC2), leftC2);
    const float ft = exp2i_s(sTop   - c2 + SHIFT);
    const float fc = exp2i_s(cornC2 - c2 + SHIFT);
    const float fl = exp2i_s(leftC2 - c2 + SHIFT);

    float prev[9];
    prev[0] = cornE * fc;
    prev[1] = t0.x * ft; prev[2] = t0.y * ft; prev[3] = t0.z * ft; prev[4] = t0.w * ft;
    prev[5] = t1.x * ft; prev[6] = t1.y * ft; prev[7] = t1.z * ft; prev[8] = t1.w * ft;
    float lE0 = left[0] * fl, lE1 = left[1] * fl, lE2 = left[2] * fl, lE3 = left[3] * fl;
    const float newCorn = prev[8];   // R[i0-1][j0+7] at aligned scale

    float right[4];
#pragma unroll
    for (int a = 0; a < 4; ++a) {
        const float4 eA = cb[2 * a], eB = cb[2 * a + 1];
        const float nl = (a == 0) ? lE0 : (a == 1) ? lE1 : (a == 2) ? lE2 : lE3;
        float carry = prev[0];
        prev[0] = nl;
        float s;
        s = (carry + prev[1]) + prev[0]; carry = prev[1]; prev[1] = eA.x * s;
        s = (carry + prev[2]) + prev[1]; carry = prev[2]; prev[2] = eA.y * s;
        s = (carry + prev[3]) + prev[2]; carry = prev[3]; prev[3] = eA.z * s;
        s = (carry + prev[4]) + prev[3]; carry = prev[4]; prev[4] = eA.w * s;
        s = (carry + prev[5]) + prev[4]; carry = prev[5]; prev[5] = eB.x * s;
        s = (carry + prev[6]) + prev[5]; carry = prev[6]; prev[6] = eB.y * s;
        s = (carry + prev[7]) + prev[6]; carry = prev[7]; prev[7] = eB.z * s;
        s = (carry + prev[8]) + prev[7];                  prev[8] = eB.w * s;
        right[a] = prev[8];
    }

    // Final cell of the whole DP: tile (127, 63), pre-renorm value, scale c2-SHIFT.
    if (tj == GTJ - 1 && ti == 127)
        *outp = -(log2f(prev[8]) + (float)(c2 - SHIFT)) * 0.69314718055994530942f;

    // ONE merged renorm over the 12 outputs (row 8 + col 4).
    float m = fmaxf(fmaxf(fmaxf(prev[1], prev[2]), fmaxf(prev[3], prev[4])),
                    fmaxf(fmaxf(prev[5], prev[6]), fmaxf(prev[7], prev[8])));
    m = fmaxf(m, fmaxf(fmaxf(right[0], right[1]), fmaxf(right[2], right[3])));
    int em = fexp(m);
    float rs = __int_as_float((127 - em) << 23);   // 2^-em
    int c2n = (m > 0.0f) ? (c2 - SHIFT + em) : C2_NEG;

    float4 o0 = make_float4(prev[1] * rs, prev[2] * rs, prev[3] * rs, prev[4] * rs);
    float4 o1 = make_float4(prev[5] * rs, prev[6] * rs, prev[7] * rs, prev[8] * rs);
    left[0] = right[0] * rs; left[1] = right[1] * rs;
    left[2] = right[2] * rs; left[3] = right[3] * rs;
    leftC2 = c2n;

    // Corner: own-exponent renorm (scale must track its magnitude).
    int ec = fexp(newCorn);
    cornE  = newCorn * __int_as_float((127 - ec) << 23);
    cornC2 = (newCorn > 0.0f) ? (c2 - SHIFT + ec) : C2_NEG;

    const int ws = act ? 2 * tj : 2 * GTJ;   // dummy slots when inactive
    rowE4[wb][ws]     = o0;
    rowE4[wb][ws + 1] = o1;
    rowC2[wb][act ? tj : GTJ] = c2n;
    __syncthreads();
}

__global__ void __launch_bounds__(128, 1)
dp_kernel(float* __restrict__ out) {
    const int b = blockIdx.x;
    const float* Eb = g_E + (size_t)b * NS * NS;

    __shared__ __align__(16) float4 rowE4[2][2 * GTJ + 2];
    __shared__ int rowC2[2][GTJ + 2];

    const int ti = threadIdx.x;
    const float* Erow0 = Eb + (size_t)(ti * 4) * NS;

    // Pre-zero both parities (i = -1 boundary: W = 0, scale C2_NEG).
    {
        float4 z = make_float4(0.f, 0.f, 0.f, 0.f);
        float4* re = &rowE4[0][0];
        for (int s = ti; s < 2 * (2 * GTJ + 2); s += 128) re[s] = z;
        int* rc = &rowC2[0][0];
        for (int s = ti; s < 2 * (GTJ + 2); s += 128) rc[s] = C2_NEG;
    }

    float4 bufA[8], bufB[8];
#pragma unroll
    for (int a = 0; a < 8; ++a) {
        bufA[a] = make_float4(0.f, 0.f, 0.f, 0.f);
        bufB[a] = bufA[a];
    }
#pragma unroll
    for (int a = 0; a < 4; ++a) {   // preload tile tj=0 (consumed by ti=0 at kd=0)
        bufA[2 * a]     = *reinterpret_cast<const float4*>(Erow0 + a * NS);
        bufA[2 * a + 1] = *reinterpret_cast<const float4*>(Erow0 + a * NS + 4);
    }

    float left[4] = {0.f, 0.f, 0.f, 0.f};
    int leftC2 = C2_NEG;
    float cornE = 0.f;
    int cornC2 = C2_NEG;

    __syncthreads();

    for (int kd = 0; kd < NDIAG; kd += 2) {
        dp_step(kd,     ti, Erow0, bufA, bufB, rowE4, rowC2,
                left, leftC2, cornE, cornC2, out + b);
        dp_step(kd + 1, ti, Erow0, bufB, bufA, rowE4, rowC2,
                left, leftC2, cornE, cornC2, out + b);
    }
}

// ---------------------------------------------------------------------------
extern "C" void kernel_launch(void* const* d_in, const int* in_sizes, int n_in,
                              void* d_out, int out_size) {
    (void)in_sizes; (void)n_in; (void)out_size;
    const float* X = (const float*)d_in[0];
    const float* Y = (const float*)d_in[1];
    float* out = (float*)d_out;

    dim3 g1(NS / 64, NS / 64, NB);   // (8, 8, 64)
    dim3 b1(16, 16);
    cdist_kernel<<<g1, b1>>>(X, Y);

    dp_kernel<<<NB, 128>>>(out);
}